// round 16
// baseline (speedup 1.0000x reference)
#include <cuda_runtime.h>

#define NEG_SLOPE 0.2f
#define MAXN 100000
#define MAXE 3200000

// ---- scratch (static __device__ arrays; no allocation anywhere) ----
__device__ __align__(16) float g_h0 [MAXN];
__device__ __align__(16) float g_h2 [MAXN * 16];
__device__ __align__(16) float g_ald2[MAXN * 4];
__device__ __align__(16) float g_h3 [MAXN * 8];
__device__ __align__(16) float g_ald3[MAXN * 2];
__device__ __align__(16) float g_x6 [MAXN * 8];
__device__ __align__(16) float g_y6 [MAXN];
__device__ __align__(8)  float g_acc[MAXN * 2];    // {dot_sum + y_sum, deg}

// ---- CSR scratch (in-adjacency, self loops INCLUDED; gathers mask s==n) ----
__device__ int g_cnt[MAXN];
__device__ int g_rs [MAXN];   // after scatter: g_rs[n] == segment END
__device__ int g_adj[MAXE];
__device__ int g_total;

__device__ __forceinline__ float lrelu(float x) { return x > 0.f ? x : NEG_SLOPE * x; }

__device__ __forceinline__ float wred8(float v) {
    v += __shfl_xor_sync(0xffffffffu, v, 4);
    v += __shfl_xor_sync(0xffffffffu, v, 2);
    v += __shfl_xor_sync(0xffffffffu, v, 1);
    return v;
}

__device__ __forceinline__ void red2(float* p, float a, float b) {
    asm volatile("red.global.add.v2.f32 [%0], {%1,%2};"
                 :: "l"(p), "f"(a), "f"(b) : "memory");
}

// ---------- K0: h0 = relu(x1@lin1w^T + b); zero cnt + scan total ----------
__global__ void k_node0(const float* __restrict__ x1,
                        const float* __restrict__ lin1w, const float* __restrict__ lin1b,
                        int N)
{
    int n = blockIdx.x * blockDim.x + threadIdx.x;
    if (n >= N) return;
    if (n == 0) g_total = 0;
    g_cnt[n] = 0;
    float h0 = __ldg(&lin1b[0]);
    #pragma unroll
    for (int i = 0; i < 7; i++) h0 = fmaf(__ldg(&x1[n * 7 + i]), __ldg(&lin1w[i]), h0);
    g_h0[n] = fmaxf(h0, 0.f);
}

// ---------- CSR build: count ALL edges by dst (2 edges/thread) ----------
__global__ void k_hist(const int* __restrict__ ei, int E)
{
    int e = (blockIdx.x * blockDim.x + threadIdx.x) * 2;
    if (e >= E) return;
    if (e + 1 < E) {
        int2 dp = __ldg((const int2*)&ei[E + e]);
        atomicAdd(&g_cnt[dp.x], 1);
        atomicAdd(&g_cnt[dp.y], 1);
    } else {
        atomicAdd(&g_cnt[__ldg(&ei[E + e])], 1);
    }
}

// ---------- single-kernel scan: block scan + atomic base (placement order free) ----------
__global__ void k_scan(int N)
{
    __shared__ int sh[1024];
    __shared__ int base;
    int i = blockIdx.x * 1024 + threadIdx.x;
    int v = (i < N) ? g_cnt[i] : 0;
    sh[threadIdx.x] = v;
    #pragma unroll
    for (int off = 1; off < 1024; off <<= 1) {
        __syncthreads();
        int t = (threadIdx.x >= off) ? sh[threadIdx.x - off] : 0;
        __syncthreads();
        sh[threadIdx.x] += t;
    }
    __syncthreads();
    if (threadIdx.x == 1023) base = atomicAdd(&g_total, sh[1023]);
    __syncthreads();
    if (i < N) g_rs[i] = base + sh[threadIdx.x] - v;   // exclusive start
}

// ---------- scatter: bump g_rs directly (ends at segment END); 2 edges/thread ----------
__global__ void k_scatter(const int* __restrict__ ei, int E)
{
    int e = (blockIdx.x * blockDim.x + threadIdx.x) * 2;
    if (e >= E) return;
    if (e + 1 < E) {
        int2 sp = __ldg((const int2*)&ei[e]);
        int2 dp = __ldg((const int2*)&ei[E + e]);
        int p0 = atomicAdd(&g_rs[dp.x], 1);
        int p1 = atomicAdd(&g_rs[dp.y], 1);
        g_adj[p0] = sp.x;
        g_adj[p1] = sp.y;
    } else {
        int s = __ldg(&ei[e]);
        int d = __ldg(&ei[E + e]);
        int p = atomicAdd(&g_rs[d], 1);
        g_adj[p] = s;
    }
}

// ---------- G1+N2: layer1 gather (rank-1, unroll x2) fused with layer2 node prep ----------
__global__ void __launch_bounds__(256) k_gat1n2(
    const float* __restrict__ W1, const float* __restrict__ as1,
    const float* __restrict__ ad1, const float* __restrict__ b1,
    const float* __restrict__ W2, const float* __restrict__ ad2, int N)
{
    int gid = blockIdx.x * blockDim.x + threadIdx.x;
    int n = gid >> 3;
    int sub = threadIdx.x & 7;
    if (n >= N) return;
    int end = __ldg(&g_rs[n]);
    int start = end - __ldg(&g_cnt[n]);
    float h0d = __ldg(&g_h0[n]);
    float kas[8], kadh[8];
    #pragma unroll
    for (int h = 0; h < 8; h++) {
        float kasv = 0.f, kadv = 0.f;
        #pragma unroll
        for (int c = 0; c < 4; c++) {
            float w = __ldg(&W1[h * 4 + c]);
            kasv = fmaf(w, __ldg(&as1[h * 4 + c]), kasv);
            kadv = fmaf(w, __ldg(&ad1[h * 4 + c]), kadv);
        }
        kas[h] = kasv; kadh[h] = kadv * h0d;
    }
    float S[8], Wv[8];
    if (sub == 0) {   // self-loop term: h0s = h0d
        #pragma unroll
        for (int h = 0; h < 8; h++) {
            float w = __expf(lrelu(fmaf(kas[h], h0d, kadh[h])));
            S[h] = w * h0d; Wv[h] = w;
        }
    } else {
        #pragma unroll
        for (int h = 0; h < 8; h++) { S[h] = 0.f; Wv[h] = 0.f; }
    }
    int i = start + sub;
    for (; i + 8 < end; i += 16) {
        int s0 = __ldg(&g_adj[i]);
        int s1 = __ldg(&g_adj[i + 8]);
        float h0a = __ldg(&g_h0[s0]);
        float h0b = __ldg(&g_h0[s1]);
        float m0 = (s0 != n) ? 1.f : 0.f;
        float m1 = (s1 != n) ? 1.f : 0.f;
        #pragma unroll
        for (int h = 0; h < 8; h++) {
            float wa = m0 * __expf(lrelu(fmaf(kas[h], h0a, kadh[h])));
            float wb = m1 * __expf(lrelu(fmaf(kas[h], h0b, kadh[h])));
            S[h] = fmaf(wa, h0a, S[h]);
            S[h] = fmaf(wb, h0b, S[h]);
            Wv[h] += wa + wb;
        }
    }
    if (i < end) {
        int s = __ldg(&g_adj[i]);
        float h0s = __ldg(&g_h0[s]);
        float m = (s != n) ? 1.f : 0.f;
        #pragma unroll
        for (int h = 0; h < 8; h++) {
            float w = m * __expf(lrelu(fmaf(kas[h], h0s, kadh[h])));
            S[h] = fmaf(w, h0s, S[h]);
            Wv[h] += w;
        }
    }
    #pragma unroll
    for (int h = 0; h < 8; h++) { S[h] = wred8(S[h]); Wv[h] = wred8(Wv[h]); }
    if (sub != 0) return;
    float x3[32];
    #pragma unroll
    for (int h = 0; h < 8; h++) {
        float r = S[h] / Wv[h];
        #pragma unroll
        for (int c = 0; c < 4; c++)
            x3[h * 4 + c] = fmaxf(fmaf(r, __ldg(&W1[h * 4 + c]), __ldg(&b1[h * 4 + c])), 0.f);
    }
    float h2[16];
    #pragma unroll
    for (int j = 0; j < 16; j++) h2[j] = 0.f;
    #pragma unroll
    for (int i2 = 0; i2 < 32; i2++) {
        float xi = x3[i2];
        #pragma unroll
        for (int j = 0; j < 16; j++) h2[j] = fmaf(xi, __ldg(&W2[i2 * 16 + j]), h2[j]);
    }
    #pragma unroll
    for (int q = 0; q < 4; q++)
        *(float4*)&g_h2[(size_t)n * 16 + q * 4] =
            make_float4(h2[q*4], h2[q*4+1], h2[q*4+2], h2[q*4+3]);
    float ald[4];
    #pragma unroll
    for (int h = 0; h < 4; h++) {
        float a = 0.f;
        #pragma unroll
        for (int c = 0; c < 4; c++) a = fmaf(h2[h * 4 + c], __ldg(&ad2[h * 4 + c]), a);
        ald[h] = a;
    }
    *(float4*)&g_ald2[(size_t)n * 4] = make_float4(ald[0], ald[1], ald[2], ald[3]);
}

// ---------- G2+N3: layer2 gather (unroll x2) fused with layer3 node prep ----------
__global__ void __launch_bounds__(256) k_gat2n3(
    const float* __restrict__ as2, const float* __restrict__ b2,
    const float* __restrict__ W3, const float* __restrict__ ad3, int N)
{
    int gid = blockIdx.x * blockDim.x + threadIdx.x;
    int n = gid >> 3;
    int sub = threadIdx.x & 7;
    if (n >= N) return;
    int end = __ldg(&g_rs[n]);
    int start = end - __ldg(&g_cnt[n]);
    float4 ad = *(const float4*)&g_ald2[(size_t)n * 4];
    float a2[16];
    #pragma unroll
    for (int j = 0; j < 16; j++) a2[j] = __ldg(&as2[j]);
    float num[16], den[4];
    #pragma unroll
    for (int j = 0; j < 16; j++) num[j] = 0.f;
    #pragma unroll
    for (int j = 0; j < 4; j++) den[j] = 0.f;

    auto body = [&](float m, const float4& h0v, const float4& h1v,
                    const float4& h2v, const float4& h3v) {
        float as0 = h0v.x*a2[0]  + h0v.y*a2[1]  + h0v.z*a2[2]  + h0v.w*a2[3];
        float as1 = h1v.x*a2[4]  + h1v.y*a2[5]  + h1v.z*a2[6]  + h1v.w*a2[7];
        float asv2= h2v.x*a2[8]  + h2v.y*a2[9]  + h2v.z*a2[10] + h2v.w*a2[11];
        float as3 = h3v.x*a2[12] + h3v.y*a2[13] + h3v.z*a2[14] + h3v.w*a2[15];
        float w0 = m * __expf(lrelu(as0 + ad.x));
        float w1 = m * __expf(lrelu(as1 + ad.y));
        float w2 = m * __expf(lrelu(asv2 + ad.z));
        float w3 = m * __expf(lrelu(as3 + ad.w));
        den[0] += w0; den[1] += w1; den[2] += w2; den[3] += w3;
        num[0]  = fmaf(w0, h0v.x, num[0]);  num[1]  = fmaf(w0, h0v.y, num[1]);
        num[2]  = fmaf(w0, h0v.z, num[2]);  num[3]  = fmaf(w0, h0v.w, num[3]);
        num[4]  = fmaf(w1, h1v.x, num[4]);  num[5]  = fmaf(w1, h1v.y, num[5]);
        num[6]  = fmaf(w1, h1v.z, num[6]);  num[7]  = fmaf(w1, h1v.w, num[7]);
        num[8]  = fmaf(w2, h2v.x, num[8]);  num[9]  = fmaf(w2, h2v.y, num[9]);
        num[10] = fmaf(w2, h2v.z, num[10]); num[11] = fmaf(w2, h2v.w, num[11]);
        num[12] = fmaf(w3, h3v.x, num[12]); num[13] = fmaf(w3, h3v.y, num[13]);
        num[14] = fmaf(w3, h3v.z, num[14]); num[15] = fmaf(w3, h3v.w, num[15]);
    };

    if (sub == 0) {
        const float4* hp = (const float4*)&g_h2[(size_t)n * 16];
        body(1.f, __ldg(hp + 0), __ldg(hp + 1), __ldg(hp + 2), __ldg(hp + 3));
    }
    int i = start + sub;
    for (; i + 8 < end; i += 16) {
        int s0 = __ldg(&g_adj[i]);
        int s1 = __ldg(&g_adj[i + 8]);
        const float4* pa = (const float4*)&g_h2[(size_t)s0 * 16];
        const float4* pb = (const float4*)&g_h2[(size_t)s1 * 16];
        float4 a0 = __ldg(pa + 0), a1 = __ldg(pa + 1), a2v = __ldg(pa + 2), a3v = __ldg(pa + 3);
        float4 b0 = __ldg(pb + 0), b1 = __ldg(pb + 1), b2v = __ldg(pb + 2), b3v = __ldg(pb + 3);
        body((s0 != n) ? 1.f : 0.f, a0, a1, a2v, a3v);
        body((s1 != n) ? 1.f : 0.f, b0, b1, b2v, b3v);
    }
    if (i < end) {
        int s = __ldg(&g_adj[i]);
        const float4* hp = (const float4*)&g_h2[(size_t)s * 16];
        body((s != n) ? 1.f : 0.f, __ldg(hp + 0), __ldg(hp + 1), __ldg(hp + 2), __ldg(hp + 3));
    }
    #pragma unroll
    for (int j = 0; j < 16; j++) num[j] = wred8(num[j]);
    #pragma unroll
    for (int j = 0; j < 4; j++) den[j] = wred8(den[j]);
    if (sub != 0) return;
    float x4[16];
    #pragma unroll
    for (int h = 0; h < 4; h++) {
        float inv = 1.f / den[h];
        #pragma unroll
        for (int c = 0; c < 4; c++)
            x4[h * 4 + c] = fmaxf(fmaf(num[h * 4 + c], inv, __ldg(&b2[h * 4 + c])), 0.f);
    }
    float h3[8];
    #pragma unroll
    for (int k = 0; k < 8; k++) h3[k] = 0.f;
    #pragma unroll
    for (int j = 0; j < 16; j++) {
        float xj = x4[j];
        #pragma unroll
        for (int k = 0; k < 8; k++) h3[k] = fmaf(xj, __ldg(&W3[j * 8 + k]), h3[k]);
    }
    *(float4*)&g_h3[(size_t)n * 8]     = make_float4(h3[0], h3[1], h3[2], h3[3]);
    *(float4*)&g_h3[(size_t)n * 8 + 4] = make_float4(h3[4], h3[5], h3[6], h3[7]);
    float al0 = 0.f, al1 = 0.f;
    #pragma unroll
    for (int c = 0; c < 4; c++) {
        al0 = fmaf(h3[c],     __ldg(&ad3[c]),     al0);
        al1 = fmaf(h3[4 + c], __ldg(&ad3[4 + c]), al1);
    }
    *(float2*)&g_ald3[(size_t)n * 2] = make_float2(al0, al1);
}

// ---------- G3+N4: layer3 gather (unroll x2) fused with x6/y6/acc init ----------
__global__ void __launch_bounds__(256) k_gat3n4(
    const float* __restrict__ as3, const float* __restrict__ b3,
    const float* __restrict__ lin2w, int N)
{
    int gid = blockIdx.x * blockDim.x + threadIdx.x;
    int n = gid >> 3;
    int sub = threadIdx.x & 7;
    if (n >= N) return;
    int end = __ldg(&g_rs[n]);
    int start = end - __ldg(&g_cnt[n]);
    float2 ad = *(const float2*)&g_ald3[(size_t)n * 2];
    float a3[8];
    #pragma unroll
    for (int j = 0; j < 8; j++) a3[j] = __ldg(&as3[j]);
    float num[8], den[2];
    #pragma unroll
    for (int j = 0; j < 8; j++) num[j] = 0.f;
    den[0] = 0.f; den[1] = 0.f;

    auto body = [&](float m, const float4& lo, const float4& hi) {
        float as0 = lo.x*a3[0] + lo.y*a3[1] + lo.z*a3[2] + lo.w*a3[3];
        float as1 = hi.x*a3[4] + hi.y*a3[5] + hi.z*a3[6] + hi.w*a3[7];
        float w0 = m * __expf(lrelu(as0 + ad.x));
        float w1 = m * __expf(lrelu(as1 + ad.y));
        den[0] += w0; den[1] += w1;
        num[0] = fmaf(w0, lo.x, num[0]); num[1] = fmaf(w0, lo.y, num[1]);
        num[2] = fmaf(w0, lo.z, num[2]); num[3] = fmaf(w0, lo.w, num[3]);
        num[4] = fmaf(w1, hi.x, num[4]); num[5] = fmaf(w1, hi.y, num[5]);
        num[6] = fmaf(w1, hi.z, num[6]); num[7] = fmaf(w1, hi.w, num[7]);
    };

    if (sub == 0) {
        body(1.f, __ldg((const float4*)&g_h3[(size_t)n * 8]),
                  __ldg((const float4*)&g_h3[(size_t)n * 8 + 4]));
    }
    int i = start + sub;
    for (; i + 8 < end; i += 16) {
        int s0 = __ldg(&g_adj[i]);
        int s1 = __ldg(&g_adj[i + 8]);
        float4 la = __ldg((const float4*)&g_h3[(size_t)s0 * 8]);
        float4 ha = __ldg((const float4*)&g_h3[(size_t)s0 * 8 + 4]);
        float4 lb = __ldg((const float4*)&g_h3[(size_t)s1 * 8]);
        float4 hb = __ldg((const float4*)&g_h3[(size_t)s1 * 8 + 4]);
        body((s0 != n) ? 1.f : 0.f, la, ha);
        body((s1 != n) ? 1.f : 0.f, lb, hb);
    }
    if (i < end) {
        int s = __ldg(&g_adj[i]);
        body((s != n) ? 1.f : 0.f,
             __ldg((const float4*)&g_h3[(size_t)s * 8]),
             __ldg((const float4*)&g_h3[(size_t)s * 8 + 4]));
    }
    #pragma unroll
    for (int j = 0; j < 8; j++) num[j] = wred8(num[j]);
    den[0] = wred8(den[0]); den[1] = wred8(den[1]);
    if (sub != 0) return;
    float inv0 = 1.f / den[0];
    float inv1 = 1.f / den[1];
    float x6[8];
    #pragma unroll
    for (int k = 0; k < 8; k++) {
        float inv = (k < 4) ? inv0 : inv1;
        x6[k] = fmaxf(fmaf(num[k], inv, __ldg(&b3[k])), 0.f);
    }
    float y6 = 0.f, selfdot = 0.f;
    #pragma unroll
    for (int k = 0; k < 8; k++) {
        y6 = fmaf(x6[k], __ldg(&lin2w[k]), y6);
        selfdot = fmaf(x6[k], x6[k], selfdot);
    }
    *(float4*)&g_x6[(size_t)n * 8]     = make_float4(x6[0], x6[1], x6[2], x6[3]);
    *(float4*)&g_x6[(size_t)n * 8 + 4] = make_float4(x6[4], x6[5], x6[6], x6[7]);
    g_y6[n] = y6;
    *(float2*)&g_acc[(size_t)n * 2] = make_float2(selfdot + y6, 1.f);
}

// ---------- GF: final scoring via in-CSR (unroll x2); red2{dot+y6d, 1} to acc[s] ----------
__global__ void __launch_bounds__(256) k_gatF(int N)
{
    int gid = blockIdx.x * blockDim.x + threadIdx.x;
    int n = gid >> 3;                      // n is the DST node; entries are sources s
    int sub = threadIdx.x & 7;
    if (n >= N) return;
    int end = __ldg(&g_rs[n]);
    int start = end - __ldg(&g_cnt[n]);
    float4 d0 = *(const float4*)&g_x6[(size_t)n * 8];
    float4 d1 = *(const float4*)&g_x6[(size_t)n * 8 + 4];
    float y6d = g_y6[n];
    int i = start + sub;
    for (; i + 8 < end; i += 16) {
        int s0 = __ldg(&g_adj[i]);
        int s1 = __ldg(&g_adj[i + 8]);
        float4 a0 = __ldg((const float4*)&g_x6[(size_t)s0 * 8]);
        float4 a1 = __ldg((const float4*)&g_x6[(size_t)s0 * 8 + 4]);
        float4 b0 = __ldg((const float4*)&g_x6[(size_t)s1 * 8]);
        float4 b1 = __ldg((const float4*)&g_x6[(size_t)s1 * 8 + 4]);
        float dta = a0.x*d0.x + a0.y*d0.y + a0.z*d0.z + a0.w*d0.w
                  + a1.x*d1.x + a1.y*d1.y + a1.z*d1.z + a1.w*d1.w;
        float dtb = b0.x*d0.x + b0.y*d0.y + b0.z*d0.z + b0.w*d0.w
                  + b1.x*d1.x + b1.y*d1.y + b1.z*d1.z + b1.w*d1.w;
        if (s0 != n) red2(g_acc + (size_t)s0 * 2, dta + y6d, 1.f);
        if (s1 != n) red2(g_acc + (size_t)s1 * 2, dtb + y6d, 1.f);
    }
    if (i < end) {
        int s = __ldg(&g_adj[i]);
        float4 a0 = __ldg((const float4*)&g_x6[(size_t)s * 8]);
        float4 a1 = __ldg((const float4*)&g_x6[(size_t)s * 8 + 4]);
        float dot = a0.x*d0.x + a0.y*d0.y + a0.z*d0.z + a0.w*d0.w
                  + a1.x*d1.x + a1.y*d1.y + a1.z*d1.z + a1.w*d1.w;
        if (s != n) red2(g_acc + (size_t)s * 2, dot + y6d, 1.f);
    }
}

// ---------- K8: out = acc.x / acc.y ----------
__global__ void k_out(float* __restrict__ out, int N)
{
    int n = blockIdx.x * blockDim.x + threadIdx.x;
    if (n >= N) return;
    float2 a = *(const float2*)&g_acc[(size_t)n * 2];
    out[n] = a.x / a.y;
}

extern "C" void kernel_launch(void* const* d_in, const int* in_sizes, int n_in,
                              void* d_out, int out_size)
{
    const float* x1 = (const float*)d_in[0];
    const int*   ei = (const int*)d_in[2];
    int wb = (in_sizes[3] == 7) ? 3 : 4;
    const float* lin1w = (const float*)d_in[wb + 0];
    const float* lin1b = (const float*)d_in[wb + 1];
    const float* lin2w = (const float*)d_in[wb + 2];
    const float* W1    = (const float*)d_in[wb + 3];
    const float* as1   = (const float*)d_in[wb + 4];
    const float* ad1   = (const float*)d_in[wb + 5];
    const float* b1    = (const float*)d_in[wb + 6];
    const float* W2    = (const float*)d_in[wb + 7];
    const float* as2   = (const float*)d_in[wb + 8];
    const float* ad2   = (const float*)d_in[wb + 9];
    const float* b2    = (const float*)d_in[wb + 10];
    const float* W3    = (const float*)d_in[wb + 11];
    const float* as3   = (const float*)d_in[wb + 12];
    const float* ad3   = (const float*)d_in[wb + 13];
    const float* b3    = (const float*)d_in[wb + 14];

    int N = in_sizes[0] / 7;
    int E = in_sizes[2] / 2;
    int nb  = (N + 255) / 256;
    int eb2 = ((E + 1) / 2 + 255) / 256;   // 2 edges/thread
    int gb  = (N * 8 + 255) / 256;         // 8 lanes per node, 4 nodes/warp
    int sb  = (N + 1023) / 1024;

    k_node0  <<<nb, 256>>>(x1, lin1w, lin1b, N);
    k_hist   <<<eb2, 256>>>(ei, E);
    k_scan   <<<sb, 1024>>>(N);
    k_scatter<<<eb2, 256>>>(ei, E);

    k_gat1n2 <<<gb, 256>>>(W1, as1, ad1, b1, W2, ad2, N);
    k_gat2n3 <<<gb, 256>>>(as2, b2, W3, ad3, N);
    k_gat3n4 <<<gb, 256>>>(as3, b3, lin2w, N);
    k_gatF   <<<gb, 256>>>(N);
    k_out    <<<nb, 256>>>((float*)d_out, N);
}